// round 1
// baseline (speedup 1.0000x reference)
#include <cuda_runtime.h>
#include <math.h>

// ---------------- problem constants ----------------
#define B_    32
#define S_    512
#define D_    512
#define NROWS (B_ * S_)      // 16384
#define H_    4
#define HD_   128
#define DFF   2048
#define NQ    8
#define NL    4
#define QKVLD 1536

// ---------------- scratch (device globals; no cudaMalloc allowed) ----------------
__device__ float g_qkv [NROWS * 3 * D_];     // 100 MB
__device__ float g_buf1[NROWS * DFF];        // 134 MB: scores (32*4*512*512 == 16384*2048), later h
__device__ float g_attn[NROWS * D_];         // attention context
__device__ float g_proj[NROWS * D_];         // after out-proj
__device__ float g_x1  [NROWS * D_];         // after ln1
__device__ float g_x2  [NROWS * D_];         // after quantum residual
__device__ float g_ffn [NROWS * D_];         // ffn2 output
__device__ float g_ang [NROWS * NQ];
__device__ float g_z   [NROWS * NQ];

// ---------------- 128x128 tile GEMM core (256 threads, 8x8 per thread) ----------------
template<bool BT>
__device__ __forceinline__ void tile128(const float* __restrict__ A,
                                        const float* __restrict__ B,
                                        int K, int lda, int ldb,
                                        float* As, float* Bs, float (&acc)[8][8]) {
    const int tid  = threadIdx.x;
    const int tr   = (tid >> 4) << 3;
    const int tc   = (tid & 15) << 3;
    const int arow = tid >> 1;
    const int acol = (tid & 1) << 2;
    const int brow = tid >> 5;         // NN: k row 0..7
    const int bcol = (tid & 31) << 2;  // NN: col 0..124

    for (int k0 = 0; k0 < K; k0 += 8) {
        float4 av = *reinterpret_cast<const float4*>(A + (size_t)arow * lda + k0 + acol);
        As[(acol + 0) * 128 + arow] = av.x;
        As[(acol + 1) * 128 + arow] = av.y;
        As[(acol + 2) * 128 + arow] = av.z;
        As[(acol + 3) * 128 + arow] = av.w;
        if (BT) {
            float4 bv = *reinterpret_cast<const float4*>(B + (size_t)arow * ldb + k0 + acol);
            Bs[(acol + 0) * 128 + arow] = bv.x;
            Bs[(acol + 1) * 128 + arow] = bv.y;
            Bs[(acol + 2) * 128 + arow] = bv.z;
            Bs[(acol + 3) * 128 + arow] = bv.w;
        } else {
            float4 bv = *reinterpret_cast<const float4*>(B + (size_t)(k0 + brow) * ldb + bcol);
            *reinterpret_cast<float4*>(&Bs[brow * 128 + bcol]) = bv;
        }
        __syncthreads();
        #pragma unroll
        for (int kk = 0; kk < 8; kk++) {
            float4 a0 = *reinterpret_cast<const float4*>(&As[kk * 128 + tr]);
            float4 a1 = *reinterpret_cast<const float4*>(&As[kk * 128 + tr + 4]);
            float4 b0 = *reinterpret_cast<const float4*>(&Bs[kk * 128 + tc]);
            float4 b1 = *reinterpret_cast<const float4*>(&Bs[kk * 128 + tc + 4]);
            float a[8] = {a0.x, a0.y, a0.z, a0.w, a1.x, a1.y, a1.z, a1.w};
            float b[8] = {b0.x, b0.y, b0.z, b0.w, b1.x, b1.y, b1.z, b1.w};
            #pragma unroll
            for (int i = 0; i < 8; i++)
                #pragma unroll
                for (int j = 0; j < 8; j++)
                    acc[i][j] = fmaf(a[i], b[j], acc[i][j]);
        }
        __syncthreads();
    }
}

// Generic C = A(MxK, row-major) * B(NxK, row-major)^T + bias, optional exact GELU
template<int EPI>  // 0: +bias, 1: +bias then gelu
__global__ void sgemm_nt(const float* __restrict__ A, const float* __restrict__ B,
                         const float* __restrict__ bias, float* __restrict__ C,
                         int N, int K) {
    __shared__ float As[8 * 128];
    __shared__ float Bs[8 * 128];
    const int m0 = blockIdx.y * 128, n0 = blockIdx.x * 128;
    float acc[8][8] = {};
    tile128<true>(A + (size_t)m0 * K, B + (size_t)n0 * K, K, K, K, As, Bs, acc);
    const int tr = (threadIdx.x >> 4) << 3, tc = (threadIdx.x & 15) << 3;
    #pragma unroll
    for (int i = 0; i < 8; i++) {
        size_t crow = (size_t)(m0 + tr + i) * N + n0 + tc;
        #pragma unroll
        for (int j = 0; j < 8; j++) {
            float v = acc[i][j] + bias[n0 + tc + j];
            if (EPI == 1) v = 0.5f * v * (1.0f + erff(v * 0.70710678118654752f));
            C[crow + j] = v;
        }
    }
}

// scores[b,h] = Q K^T / sqrt(hd)   (M=N=512, K=128, strided into qkv)
__global__ void attn_scores_k(const float* __restrict__ qkv, float* __restrict__ sc) {
    __shared__ float As[8 * 128];
    __shared__ float Bs[8 * 128];
    const int bh = blockIdx.z, b = bh >> 2, h = bh & 3;
    const float* base = qkv + (size_t)b * S_ * QKVLD;
    const int m0 = blockIdx.y * 128, n0 = blockIdx.x * 128;
    float acc[8][8] = {};
    tile128<true>(base + (size_t)m0 * QKVLD + h * HD_,
                  base + (size_t)n0 * QKVLD + D_ + h * HD_,
                  HD_, QKVLD, QKVLD, As, Bs, acc);
    float* C = sc + (size_t)bh * S_ * S_;
    const float alpha = 0.08838834764831845f;  // 1/sqrt(128)
    const int tr = (threadIdx.x >> 4) << 3, tc = (threadIdx.x & 15) << 3;
    #pragma unroll
    for (int i = 0; i < 8; i++)
        #pragma unroll
        for (int j = 0; j < 8; j++)
            C[(size_t)(m0 + tr + i) * S_ + n0 + tc + j] = acc[i][j] * alpha;
}

// o[b,h] = P V   (M=512, N=128, K=512); writes back in (B,S,H,hd) layout
__global__ void attn_pv_k(const float* __restrict__ sc, const float* __restrict__ qkv,
                          float* __restrict__ attn) {
    __shared__ float As[8 * 128];
    __shared__ float Bs[8 * 128];
    const int bh = blockIdx.z, b = bh >> 2, h = bh & 3;
    const int m0 = blockIdx.y * 128;
    float acc[8][8] = {};
    tile128<false>(sc + (size_t)bh * S_ * S_ + (size_t)m0 * S_,
                   qkv + (size_t)b * S_ * QKVLD + 2 * D_ + h * HD_,
                   S_, S_, QKVLD, As, Bs, acc);
    float* C = attn + (size_t)(b * S_ + m0) * D_ + h * HD_;
    const int tr = (threadIdx.x >> 4) << 3, tc = (threadIdx.x & 15) << 3;
    #pragma unroll
    for (int i = 0; i < 8; i++)
        #pragma unroll
        for (int j = 0; j < 8; j++)
            C[(size_t)(tr + i) * D_ + tc + j] = acc[i][j];
}

// ---------------- reductions / norms ----------------
__device__ __forceinline__ float block_reduce_sum(float v, float* red) {
    const int t = threadIdx.x;
    red[t] = v;
    __syncthreads();
    for (int s = 128; s > 0; s >>= 1) {
        if (t < s) red[t] += red[t + s];
        __syncthreads();
    }
    float r = red[0];
    __syncthreads();
    return r;
}

__global__ void softmax_k(float* __restrict__ sc) {
    __shared__ float red[256];
    const size_t row = blockIdx.x;
    float* p = sc + row * 512;
    const int t = threadIdx.x;
    float v0 = p[t], v1 = p[t + 256];
    red[t] = fmaxf(v0, v1);
    __syncthreads();
    for (int s = 128; s > 0; s >>= 1) {
        if (t < s) red[t] = fmaxf(red[t], red[t + s]);
        __syncthreads();
    }
    float mx = red[0];
    __syncthreads();
    float e0 = expf(v0 - mx), e1 = expf(v1 - mx);
    float inv = 1.0f / block_reduce_sum(e0 + e1, red);
    p[t] = e0 * inv;
    p[t + 256] = e1 * inv;
}

// out = LN(a + b) * g + be, rows of 512
__global__ void add_ln_k(const float* __restrict__ a, const float* __restrict__ b,
                         const float* __restrict__ g, const float* __restrict__ be,
                         float* __restrict__ out) {
    __shared__ float red[256];
    const size_t row = blockIdx.x;
    const int t = threadIdx.x;
    float v0 = a[row * 512 + t] + b[row * 512 + t];
    float v1 = a[row * 512 + t + 256] + b[row * 512 + t + 256];
    float mean = block_reduce_sum(v0 + v1, red) * (1.0f / 512.0f);
    float d0 = v0 - mean, d1 = v1 - mean;
    float rstd = rsqrtf(block_reduce_sum(d0 * d0 + d1 * d1, red) * (1.0f / 512.0f) + 1e-5f);
    out[row * 512 + t]       = d0 * rstd * g[t] + be[t];
    out[row * 512 + t + 256] = d1 * rstd * g[t + 256] + be[t + 256];
}

// angles = LN3(x1) @ qin_w^T + qin_b   (8 outputs per row; one warp per output)
__global__ void ln3_qin_k(const float* __restrict__ x1, const float* __restrict__ g,
                          const float* __restrict__ be, const float* __restrict__ qw,
                          const float* __restrict__ qb, float* __restrict__ ang) {
    __shared__ float rowv[512];
    __shared__ float red[256];
    const size_t row = blockIdx.x;
    const float* p = x1 + row * 512;
    const int t = threadIdx.x;
    float v0 = p[t], v1 = p[t + 256];
    rowv[t] = v0;
    rowv[t + 256] = v1;
    float mean = block_reduce_sum(v0 + v1, red) * (1.0f / 512.0f);
    float d0 = v0 - mean, d1 = v1 - mean;
    float rstd = rsqrtf(block_reduce_sum(d0 * d0 + d1 * d1, red) * (1.0f / 512.0f) + 1e-5f);
    const int w = t >> 5, lane = t & 31;
    float dot = 0.0f;
    for (int k = lane; k < 512; k += 32) {
        float xn = (rowv[k] - mean) * rstd * g[k] + be[k];
        dot = fmaf(xn, qw[w * 512 + k], dot);
    }
    #pragma unroll
    for (int o = 16; o > 0; o >>= 1) dot += __shfl_xor_sync(0xffffffffu, dot, o);
    if (lane == 0) ang[row * 8 + w] = dot + qb[w];
}

// ---------------- 8-qubit statevector simulator (one warp per token) ----------------
__device__ __forceinline__ void rx_gate(float2* s, int pos, float c, float sn, int lane) {
    const int stride = 1 << pos;
    for (int p = lane; p < 128; p += 32) {
        int i0 = ((p >> pos) << (pos + 1)) | (p & (stride - 1));
        int i1 = i0 | stride;
        float2 a = s[i0], b = s[i1];
        s[i0] = make_float2(c * a.x + sn * b.y, c * a.y - sn * b.x);
        s[i1] = make_float2(sn * a.y + c * b.x, -sn * a.x + c * b.y);
    }
}

__device__ __forceinline__ void rz_gate(float2* s, int pos, float c, float sn, int lane) {
    for (int i = lane; i < 256; i += 32) {
        float2 a = s[i];
        if (i & (1 << pos)) s[i] = make_float2(a.x * c - a.y * sn, a.y * c + a.x * sn);
        else                s[i] = make_float2(a.x * c + a.y * sn, a.y * c - a.x * sn);
    }
}

__device__ __forceinline__ void cnot_gate(float2* s, int pt, int lane) {  // ctrl bit = pt+1
    for (int p = lane; p < 64; p += 32) {
        int lower = p & ((1 << pt) - 1);
        int upper = p >> pt;
        int base = (upper << (pt + 2)) | lower;
        int i2 = base | (2 << pt);
        int i3 = base | (3 << pt);
        float2 tmp = s[i2];
        s[i2] = s[i3];
        s[i3] = tmp;
    }
}

__global__ void quantum_k(const float* __restrict__ angles, const float* __restrict__ qw,
                          float* __restrict__ zout) {
    __shared__ float2 st[8][256];
    const int warp = threadIdx.x >> 5, lane = threadIdx.x & 31;
    const size_t row = (size_t)blockIdx.x * 8 + warp;
    float2* s = st[warp];
    for (int i = lane; i < 256; i += 32) s[i] = make_float2(0.0f, 0.0f);
    __syncwarp();
    if (lane == 0) s[0] = make_float2(1.0f, 0.0f);
    __syncwarp();
    // input encoding: RX(theta_q) then RZ(theta_q) on each wire
    for (int q = 0; q < 8; q++) {
        float th = 0.5f * angles[row * 8 + q];
        float sn, c;
        sincosf(th, &sn, &c);
        rx_gate(s, 7 - q, c, sn, lane);
        __syncwarp();
        rz_gate(s, 7 - q, c, sn, lane);
        __syncwarp();
    }
    // variational layers
    for (int l = 0; l < NL; l++) {
        for (int q = 0; q < 8; q++) {
            float snx, cx;
            sincosf(0.5f * qw[l * 16 + q], &snx, &cx);
            rx_gate(s, 7 - q, cx, snx, lane);
            __syncwarp();
            float snz, cz;
            sincosf(0.5f * qw[l * 16 + 8 + q], &snz, &cz);
            rz_gate(s, 7 - q, cz, snz, lane);
            __syncwarp();
        }
        for (int ctrl = 0; ctrl < 7; ctrl++) {
            cnot_gate(s, 6 - ctrl, lane);
            __syncwarp();
        }
    }
    // <Z_q> = sum_i (+-) |amp_i|^2, sign by bit (7-q)
    float acc[8] = {0, 0, 0, 0, 0, 0, 0, 0};
    for (int i = lane; i < 256; i += 32) {
        float2 a = s[i];
        float pr = a.x * a.x + a.y * a.y;
        #pragma unroll
        for (int q = 0; q < 8; q++)
            acc[q] += (i & (1 << (7 - q))) ? -pr : pr;
    }
    #pragma unroll
    for (int q = 0; q < 8; q++)
        #pragma unroll
        for (int o = 16; o > 0; o >>= 1)
            acc[q] += __shfl_xor_sync(0xffffffffu, acc[q], o);
    if (lane == 0) {
        #pragma unroll
        for (int q = 0; q < 8; q++) zout[row * 8 + q] = acc[q];
    }
}

// x2 = x1 + z @ qout_w^T + qout_b
__global__ void qout_resid_k(const float* __restrict__ x1, const float* __restrict__ z,
                             const float* __restrict__ w, const float* __restrict__ bias,
                             float* __restrict__ x2) {
    __shared__ float zs[8];
    const size_t row = blockIdx.x;
    if (threadIdx.x < 8) zs[threadIdx.x] = z[row * 8 + threadIdx.x];
    __syncthreads();
    for (int j = threadIdx.x; j < 512; j += 256) {
        const float* wj = w + j * 8;
        float acc = bias[j];
        #pragma unroll
        for (int q = 0; q < 8; q++) acc = fmaf(zs[q], wj[q], acc);
        x2[row * 512 + j] = x1[row * 512 + j] + acc;
    }
}

// ---------------- launch ----------------
extern "C" void kernel_launch(void* const* d_in, const int* in_sizes, int n_in,
                              void* d_out, int out_size) {
    const float* x          = (const float*)d_in[0];
    const float* attn_in_w  = (const float*)d_in[1];
    const float* attn_in_b  = (const float*)d_in[2];
    const float* attn_out_w = (const float*)d_in[3];
    const float* attn_out_b = (const float*)d_in[4];
    const float* ln1_g      = (const float*)d_in[5];
    const float* ln1_b      = (const float*)d_in[6];
    const float* ln2_g      = (const float*)d_in[7];
    const float* ln2_b      = (const float*)d_in[8];
    const float* ln3_g      = (const float*)d_in[9];
    const float* ln3_b      = (const float*)d_in[10];
    const float* qin_w      = (const float*)d_in[11];
    const float* qin_b      = (const float*)d_in[12];
    const float* qweights   = (const float*)d_in[13];
    const float* qout_w     = (const float*)d_in[14];
    const float* qout_b     = (const float*)d_in[15];
    const float* ffn_w1     = (const float*)d_in[16];
    const float* ffn_b1     = (const float*)d_in[17];
    const float* ffn_w2     = (const float*)d_in[18];
    const float* ffn_b2     = (const float*)d_in[19];
    float* out = (float*)d_out;

    float *qkv, *buf1, *attn, *proj, *x1, *x2, *ffn, *ang, *z;
    cudaGetSymbolAddress((void**)&qkv,  g_qkv);
    cudaGetSymbolAddress((void**)&buf1, g_buf1);
    cudaGetSymbolAddress((void**)&attn, g_attn);
    cudaGetSymbolAddress((void**)&proj, g_proj);
    cudaGetSymbolAddress((void**)&x1,   g_x1);
    cudaGetSymbolAddress((void**)&x2,   g_x2);
    cudaGetSymbolAddress((void**)&ffn,  g_ffn);
    cudaGetSymbolAddress((void**)&ang,  g_ang);
    cudaGetSymbolAddress((void**)&z,    g_z);

    const dim3 blk(256);

    // QKV projection: (16384 x 512) @ (1536 x 512)^T
    sgemm_nt<0><<<dim3(QKVLD / 128, NROWS / 128), blk>>>(x, attn_in_w, attn_in_b, qkv, QKVLD, D_);
    // attention
    attn_scores_k<<<dim3(4, 4, B_ * H_), blk>>>(qkv, buf1);
    softmax_k<<<B_ * H_ * S_, blk>>>(buf1);
    attn_pv_k<<<dim3(1, 4, B_ * H_), blk>>>(buf1, qkv, attn);
    // out projection
    sgemm_nt<0><<<dim3(D_ / 128, NROWS / 128), blk>>>(attn, attn_out_w, attn_out_b, proj, D_, D_);
    // x1 = LN1(x + proj)
    add_ln_k<<<NROWS, blk>>>(x, proj, ln1_g, ln1_b, x1);
    // angles = LN3(x1) @ qin_w^T + qin_b
    ln3_qin_k<<<NROWS, blk>>>(x1, ln3_g, ln3_b, qin_w, qin_b, ang);
    // quantum expectation values
    quantum_k<<<NROWS / 8, blk>>>(ang, qweights, z);
    // x2 = x1 + z @ qout_w^T + qout_b
    qout_resid_k<<<NROWS, blk>>>(x1, z, qout_w, qout_b, x2);
    // FFN: h = gelu(x2 @ w1^T + b1) ; ffn = h @ w2^T + b2    (h reuses buf1)
    sgemm_nt<1><<<dim3(DFF / 128, NROWS / 128), blk>>>(x2, ffn_w1, ffn_b1, buf1, DFF, D_);
    sgemm_nt<0><<<dim3(D_ / 128, NROWS / 128), blk>>>(buf1, ffn_w2, ffn_b2, ffn, D_, DFF);
    // out = LN2(x2 + ffn)
    add_ln_k<<<NROWS, blk>>>(x2, ffn, ln2_g, ln2_b, out);
}

// round 2
// speedup vs baseline: 2.4186x; 2.4186x over previous
#include <cuda_runtime.h>
#include <math.h>
#include <stdint.h>

// ---------------- problem constants ----------------
#define B_    32
#define S_    512
#define D_    512
#define NROWS (B_ * S_)      // 16384
#define H_    4
#define HD_   128
#define DFF   2048
#define NQ    8
#define NL    4
#define QKVLD 1536

// ---------------- scratch (device globals; no cudaMalloc allowed) ----------------
__device__ float g_qkv [NROWS * 3 * D_];
__device__ float g_buf1[NROWS * DFF];        // scores/probs (32*4*512*512), later h
__device__ float g_vt  [B_ * H_ * HD_ * S_]; // V transposed per (b,h): [128][512]
__device__ float g_attn[NROWS * D_];
__device__ float g_proj[NROWS * D_];
__device__ float g_x1  [NROWS * D_];
__device__ float g_x2  [NROWS * D_];
__device__ float g_ffn [NROWS * D_];
__device__ float g_ang [NROWS * NQ];
__device__ float g_z   [NROWS * NQ];

// ---------------- cp.async helpers ----------------
__device__ __forceinline__ void cp16(uint32_t dst, const void* src) {
    asm volatile("cp.async.cg.shared.global [%0], [%1], 16;" :: "r"(dst), "l"(src));
}
__device__ __forceinline__ void cp_commit() {
    asm volatile("cp.async.commit_group;");
}
template<int N> __device__ __forceinline__ void cp_wait() {
    asm volatile("cp.async.wait_group %0;" :: "n"(N));
}
__device__ __forceinline__ uint32_t tf32_of(float f) {
    uint32_t u;
    asm("cvt.rna.tf32.f32 %0, %1;" : "=r"(u) : "f"(f));
    return u;
}
__device__ __forceinline__ void mma_tf32(float (&c)[4], const uint32_t (&a)[4], const uint32_t (&b)[2]) {
    asm volatile(
        "mma.sync.aligned.m16n8k8.row.col.f32.tf32.tf32.f32 "
        "{%0,%1,%2,%3}, {%4,%5,%6,%7}, {%8,%9}, {%0,%1,%2,%3};"
        : "+f"(c[0]), "+f"(c[1]), "+f"(c[2]), "+f"(c[3])
        : "r"(a[0]), "r"(a[1]), "r"(a[2]), "r"(a[3]), "r"(b[0]), "r"(b[1]));
}

// ---------------- unified TF32 tensor-core GEMM ----------------
// C[M,N] = alpha * A[M,K] * B[N,K]^T (+bias) (+gelu), row-major, batched by blockIdx.z=(b*4+h)
// Block tile 128x128, BK=16, 256 threads, 8 warps of 64x32.
// Both A and B tiles stored in smem as [row][k] with row stride 20 (conflict-free fragment LDS).
#define SSTR 20
template<int EPI>  // 0: *alpha ; 1: +bias ; 2: +bias then exact gelu
__global__ void __launch_bounds__(256)
gemm_tf32(const float* __restrict__ A, int lda, long long saB, long long saH,
          const float* __restrict__ B, int ldb, long long sbB, long long sbH,
          float* __restrict__ C, int ldc, long long scB, long long scH,
          int K, const float* __restrict__ bias, float alpha) {
    __shared__ float As[2][128 * SSTR];
    __shared__ float Bs[2][128 * SSTR];

    const int z = blockIdx.z, zb = z >> 2, zh = z & 3;
    const float* Ab = A + (long long)zb * saB + (long long)zh * saH + (size_t)blockIdx.y * 128 * lda;
    const float* Bb = B + (long long)zb * sbB + (long long)zh * sbH + (size_t)blockIdx.x * 128 * ldb;
    float* Cb = C + (long long)zb * scB + (long long)zh * scH;

    const int tid = threadIdx.x;
    const int lrow = tid >> 1;          // 0..127
    const int lq   = (tid & 1) * 8;     // 0 or 8
    const int lane = tid & 31, wid = tid >> 5;
    const int warp_m = wid & 1, warp_n = wid >> 1;
    const int mbase = warp_m * 64, nbase = warp_n * 32;
    const int gi = lane >> 2, ti = lane & 3;

    const uint32_t sA0 = (uint32_t)__cvta_generic_to_shared(&As[0][0]);
    const uint32_t sB0 = (uint32_t)__cvta_generic_to_shared(&Bs[0][0]);
    const uint32_t soff = (uint32_t)(lrow * SSTR + lq) * 4;
    const uint32_t bufstep = 128 * SSTR * 4;

    float acc[4][4][4] = {};

    const int KT = K / 16;
    // prologue
    {
        const float* ap = Ab + (size_t)lrow * lda + lq;
        const float* bp = Bb + (size_t)lrow * ldb + lq;
        cp16(sA0 + soff, ap);       cp16(sA0 + soff + 16, ap + 4);
        cp16(sB0 + soff, bp);       cp16(sB0 + soff + 16, bp + 4);
        cp_commit();
    }
    for (int kt = 0; kt < KT; kt++) {
        const int nxt = kt + 1;
        if (nxt < KT) {
            const int nb = nxt & 1;
            const float* ap = Ab + (size_t)lrow * lda + nxt * 16 + lq;
            const float* bp = Bb + (size_t)lrow * ldb + nxt * 16 + lq;
            cp16(sA0 + nb * bufstep + soff, ap);       cp16(sA0 + nb * bufstep + soff + 16, ap + 4);
            cp16(sB0 + nb * bufstep + soff, bp);       cp16(sB0 + nb * bufstep + soff + 16, bp + 4);
            cp_commit();
            cp_wait<1>();
        } else {
            cp_wait<0>();
        }
        __syncthreads();
        const float* as = As[kt & 1];
        const float* bs = Bs[kt & 1];
        #pragma unroll
        for (int hk = 0; hk < 2; hk++) {
            const int kk = hk * 8 + ti;
            uint32_t afr[4][4], bfr[4][2];
            #pragma unroll
            for (int mf = 0; mf < 4; mf++) {
                const float* ap = as + (mbase + mf * 16 + gi) * SSTR + kk;
                afr[mf][0] = tf32_of(ap[0]);
                afr[mf][1] = tf32_of(ap[8 * SSTR]);
                afr[mf][2] = tf32_of(ap[4]);
                afr[mf][3] = tf32_of(ap[8 * SSTR + 4]);
            }
            #pragma unroll
            for (int nf = 0; nf < 4; nf++) {
                const float* bp = bs + (nbase + nf * 8 + gi) * SSTR + kk;
                bfr[nf][0] = tf32_of(bp[0]);
                bfr[nf][1] = tf32_of(bp[4]);
            }
            #pragma unroll
            for (int mf = 0; mf < 4; mf++)
                #pragma unroll
                for (int nf = 0; nf < 4; nf++)
                    mma_tf32(acc[mf][nf], afr[mf], bfr[nf]);
        }
        __syncthreads();
    }

    // epilogue
    #pragma unroll
    for (int mf = 0; mf < 4; mf++) {
        const int row = blockIdx.y * 128 + mbase + mf * 16 + gi;
        #pragma unroll
        for (int nf = 0; nf < 4; nf++) {
            const int col = blockIdx.x * 128 + nbase + nf * 8 + ti * 2;
            float v0 = acc[mf][nf][0], v1 = acc[mf][nf][1];
            float v2 = acc[mf][nf][2], v3 = acc[mf][nf][3];
            if (EPI == 0) {
                v0 *= alpha; v1 *= alpha; v2 *= alpha; v3 *= alpha;
            } else {
                const float b0 = bias[col], b1 = bias[col + 1];
                v0 += b0; v1 += b1; v2 += b0; v3 += b1;
                if (EPI == 2) {
                    v0 = 0.5f * v0 * (1.0f + erff(v0 * 0.70710678118654752f));
                    v1 = 0.5f * v1 * (1.0f + erff(v1 * 0.70710678118654752f));
                    v2 = 0.5f * v2 * (1.0f + erff(v2 * 0.70710678118654752f));
                    v3 = 0.5f * v3 * (1.0f + erff(v3 * 0.70710678118654752f));
                }
            }
            *reinterpret_cast<float2*>(Cb + (size_t)row * ldc + col)       = make_float2(v0, v1);
            *reinterpret_cast<float2*>(Cb + (size_t)(row + 8) * ldc + col) = make_float2(v2, v3);
        }
    }
}

// ---------------- V transpose: vt[bh][n][s] = qkv.v[b][s][h][n] ----------------
__global__ void vtrans_k(const float* __restrict__ qkv, float* __restrict__ vt) {
    __shared__ float t[32][33];
    const int bh = blockIdx.z, b = bh >> 2, h = bh & 3;
    const int s0 = blockIdx.x * 32, n0 = blockIdx.y * 32;
    const float* src = qkv + (size_t)b * S_ * QKVLD + 2 * D_ + h * HD_;
    const int tx = threadIdx.x, ty = threadIdx.y;
    #pragma unroll
    for (int i = 0; i < 32; i += 8)
        t[ty + i][tx] = src[(size_t)(s0 + ty + i) * QKVLD + n0 + tx];
    __syncthreads();
    float* dst = vt + (size_t)bh * HD_ * S_;
    #pragma unroll
    for (int i = 0; i < 32; i += 8)
        dst[(size_t)(n0 + ty + i) * S_ + s0 + tx] = t[tx][ty + i];
}

// ---------------- reductions / norms ----------------
__device__ __forceinline__ float block_reduce_sum(float v, float* red) {
    const int t = threadIdx.x;
    red[t] = v;
    __syncthreads();
    for (int s = 128; s > 0; s >>= 1) {
        if (t < s) red[t] += red[t + s];
        __syncthreads();
    }
    float r = red[0];
    __syncthreads();
    return r;
}

__global__ void softmax_k(float* __restrict__ sc) {
    __shared__ float red[256];
    const size_t row = blockIdx.x;
    float* p = sc + row * 512;
    const int t = threadIdx.x;
    float v0 = p[t], v1 = p[t + 256];
    red[t] = fmaxf(v0, v1);
    __syncthreads();
    for (int s = 128; s > 0; s >>= 1) {
        if (t < s) red[t] = fmaxf(red[t], red[t + s]);
        __syncthreads();
    }
    float mx = red[0];
    __syncthreads();
    float e0 = expf(v0 - mx), e1 = expf(v1 - mx);
    float inv = 1.0f / block_reduce_sum(e0 + e1, red);
    p[t] = e0 * inv;
    p[t + 256] = e1 * inv;
}

__global__ void add_ln_k(const float* __restrict__ a, const float* __restrict__ b,
                         const float* __restrict__ g, const float* __restrict__ be,
                         float* __restrict__ out) {
    __shared__ float red[256];
    const size_t row = blockIdx.x;
    const int t = threadIdx.x;
    float v0 = a[row * 512 + t] + b[row * 512 + t];
    float v1 = a[row * 512 + t + 256] + b[row * 512 + t + 256];
    float mean = block_reduce_sum(v0 + v1, red) * (1.0f / 512.0f);
    float d0 = v0 - mean, d1 = v1 - mean;
    float rstd = rsqrtf(block_reduce_sum(d0 * d0 + d1 * d1, red) * (1.0f / 512.0f) + 1e-5f);
    out[row * 512 + t]       = d0 * rstd * g[t] + be[t];
    out[row * 512 + t + 256] = d1 * rstd * g[t + 256] + be[t + 256];
}

__global__ void ln3_qin_k(const float* __restrict__ x1, const float* __restrict__ g,
                          const float* __restrict__ be, const float* __restrict__ qw,
                          const float* __restrict__ qb, float* __restrict__ ang) {
    __shared__ float rowv[512];
    __shared__ float red[256];
    const size_t row = blockIdx.x;
    const float* p = x1 + row * 512;
    const int t = threadIdx.x;
    float v0 = p[t], v1 = p[t + 256];
    rowv[t] = v0;
    rowv[t + 256] = v1;
    float mean = block_reduce_sum(v0 + v1, red) * (1.0f / 512.0f);
    float d0 = v0 - mean, d1 = v1 - mean;
    float rstd = rsqrtf(block_reduce_sum(d0 * d0 + d1 * d1, red) * (1.0f / 512.0f) + 1e-5f);
    const int w = t >> 5, lane = t & 31;
    float dot = 0.0f;
    for (int k = lane; k < 512; k += 32) {
        float xn = (rowv[k] - mean) * rstd * g[k] + be[k];
        dot = fmaf(xn, qw[w * 512 + k], dot);
    }
    #pragma unroll
    for (int o = 16; o > 0; o >>= 1) dot += __shfl_xor_sync(0xffffffffu, dot, o);
    if (lane == 0) ang[row * 8 + w] = dot + qb[w];
}

// ---------------- 8-qubit statevector simulator (one warp per token) ----------------
__device__ __forceinline__ void rx_gate(float2* s, int pos, float c, float sn, int lane) {
    const int stride = 1 << pos;
    for (int p = lane; p < 128; p += 32) {
        int i0 = ((p >> pos) << (pos + 1)) | (p & (stride - 1));
        int i1 = i0 | stride;
        float2 a = s[i0], b = s[i1];
        s[i0] = make_float2(c * a.x + sn * b.y, c * a.y - sn * b.x);
        s[i1] = make_float2(sn * a.y + c * b.x, -sn * a.x + c * b.y);
    }
}
__device__ __forceinline__ void rz_gate(float2* s, int pos, float c, float sn, int lane) {
    for (int i = lane; i < 256; i += 32) {
        float2 a = s[i];
        if (i & (1 << pos)) s[i] = make_float2(a.x * c - a.y * sn, a.y * c + a.x * sn);
        else                s[i] = make_float2(a.x * c + a.y * sn, a.y * c - a.x * sn);
    }
}
__device__ __forceinline__ void cnot_gate(float2* s, int pt, int lane) {
    for (int p = lane; p < 64; p += 32) {
        int lower = p & ((1 << pt) - 1);
        int upper = p >> pt;
        int base = (upper << (pt + 2)) | lower;
        int i2 = base | (2 << pt);
        int i3 = base | (3 << pt);
        float2 tmp = s[i2];
        s[i2] = s[i3];
        s[i3] = tmp;
    }
}
__global__ void quantum_k(const float* __restrict__ angles, const float* __restrict__ qw,
                          float* __restrict__ zout) {
    __shared__ float2 st[8][256];
    const int warp = threadIdx.x >> 5, lane = threadIdx.x & 31;
    const size_t row = (size_t)blockIdx.x * 8 + warp;
    float2* s = st[warp];
    for (int i = lane; i < 256; i += 32) s[i] = make_float2(0.0f, 0.0f);
    __syncwarp();
    if (lane == 0) s[0] = make_float2(1.0f, 0.0f);
    __syncwarp();
    for (int q = 0; q < 8; q++) {
        float th = 0.5f * angles[row * 8 + q];
        float sn, c;
        sincosf(th, &sn, &c);
        rx_gate(s, 7 - q, c, sn, lane);
        __syncwarp();
        rz_gate(s, 7 - q, c, sn, lane);
        __syncwarp();
    }
    for (int l = 0; l < NL; l++) {
        for (int q = 0; q < 8; q++) {
            float snx, cx;
            sincosf(0.5f * qw[l * 16 + q], &snx, &cx);
            rx_gate(s, 7 - q, cx, snx, lane);
            __syncwarp();
            float snz, cz;
            sincosf(0.5f * qw[l * 16 + 8 + q], &snz, &cz);
            rz_gate(s, 7 - q, cz, snz, lane);
            __syncwarp();
        }
        for (int ctrl = 0; ctrl < 7; ctrl++) {
            cnot_gate(s, 6 - ctrl, lane);
            __syncwarp();
        }
    }
    float acc[8] = {0, 0, 0, 0, 0, 0, 0, 0};
    for (int i = lane; i < 256; i += 32) {
        float2 a = s[i];
        float pr = a.x * a.x + a.y * a.y;
        #pragma unroll
        for (int q = 0; q < 8; q++)
            acc[q] += (i & (1 << (7 - q))) ? -pr : pr;
    }
    #pragma unroll
    for (int q = 0; q < 8; q++)
        #pragma unroll
        for (int o = 16; o > 0; o >>= 1)
            acc[q] += __shfl_xor_sync(0xffffffffu, acc[q], o);
    if (lane == 0) {
        #pragma unroll
        for (int q = 0; q < 8; q++) zout[row * 8 + q] = acc[q];
    }
}

__global__ void qout_resid_k(const float* __restrict__ x1, const float* __restrict__ z,
                             const float* __restrict__ w, const float* __restrict__ bias,
                             float* __restrict__ x2) {
    __shared__ float zs[8];
    const size_t row = blockIdx.x;
    if (threadIdx.x < 8) zs[threadIdx.x] = z[row * 8 + threadIdx.x];
    __syncthreads();
    for (int j = threadIdx.x; j < 512; j += 256) {
        const float* wj = w + j * 8;
        float acc = bias[j];
        #pragma unroll
        for (int q = 0; q < 8; q++) acc = fmaf(zs[q], wj[q], acc);
        x2[row * 512 + j] = x1[row * 512 + j] + acc;
    }
}

// ---------------- launch ----------------
extern "C" void kernel_launch(void* const* d_in, const int* in_sizes, int n_in,
                              void* d_out, int out_size) {
    const float* x          = (const float*)d_in[0];
    const float* attn_in_w  = (const float*)d_in[1];
    const float* attn_in_b  = (const float*)d_in[2];
    const float* attn_out_w = (const float*)d_in[3];
    const float* attn_out_b = (const float*)d_in[4];
    const float* ln1_g      = (const float*)d_in[5];
    const float* ln1_b      = (const float*)d_in[6];
    const float* ln2_g      = (const float*)d_in[7];
    const float* ln2_b      = (const float*)d_in[8];
    const float* ln3_g      = (const float*)d_in[9];
    const float* ln3_b      = (const float*)d_in[10];
    const float* qin_w      = (const float*)d_in[11];
    const float* qin_b      = (const float*)d_in[12];
    const float* qweights   = (const float*)d_in[13];
    const float* qout_w     = (const float*)d_in[14];
    const float* qout_b     = (const float*)d_in[15];
    const float* ffn_w1     = (const float*)d_in[16];
    const float* ffn_b1     = (const float*)d_in[17];
    const float* ffn_w2     = (const float*)d_in[18];
    const float* ffn_b2     = (const float*)d_in[19];
    float* out = (float*)d_out;

    float *qkv, *buf1, *vt, *attn, *proj, *x1, *x2, *ffn, *ang, *z;
    cudaGetSymbolAddress((void**)&qkv,  g_qkv);
    cudaGetSymbolAddress((void**)&buf1, g_buf1);
    cudaGetSymbolAddress((void**)&vt,   g_vt);
    cudaGetSymbolAddress((void**)&attn, g_attn);
    cudaGetSymbolAddress((void**)&proj, g_proj);
    cudaGetSymbolAddress((void**)&x1,   g_x1);
    cudaGetSymbolAddress((void**)&x2,   g_x2);
    cudaGetSymbolAddress((void**)&ffn,  g_ffn);
    cudaGetSymbolAddress((void**)&ang,  g_ang);
    cudaGetSymbolAddress((void**)&z,    g_z);

    const dim3 blk(256);
    const long long SS = (long long)S_ * S_;

    // QKV projection: (16384 x 512) @ (1536 x 512)^T + bias
    gemm_tf32<1><<<dim3(QKVLD / 128, NROWS / 128, 1), blk>>>(
        x, D_, 0, 0, attn_in_w, D_, 0, 0, qkv, QKVLD, 0, 0, D_, attn_in_b, 1.0f);
    // scores = Q K^T / sqrt(hd), batched over 128 (b,h)
    gemm_tf32<0><<<dim3(4, 4, B_ * H_), blk>>>(
        qkv, QKVLD, (long long)S_ * QKVLD, HD_,
        qkv + D_, QKVLD, (long long)S_ * QKVLD, HD_,
        buf1, S_, 4 * SS, SS, HD_, nullptr, 0.08838834764831845f);
    softmax_k<<<B_ * H_ * S_, blk>>>(buf1);
    // transpose V
    vtrans_k<<<dim3(S_ / 32, HD_ / 32, B_ * H_), dim3(32, 8)>>>(qkv, vt);
    // o = P V  (N=128 per head)
    gemm_tf32<0><<<dim3(1, 4, B_ * H_), blk>>>(
        buf1, S_, 4 * SS, SS,
        vt, S_, (long long)H_ * HD_ * S_, (long long)HD_ * S_,
        attn, D_, (long long)S_ * D_, HD_, S_, nullptr, 1.0f);
    // out projection
    gemm_tf32<1><<<dim3(D_ / 128, NROWS / 128, 1), blk>>>(
        attn, D_, 0, 0, attn_out_w, D_, 0, 0, proj, D_, 0, 0, D_, attn_out_b, 1.0f);
    // x1 = LN1(x + proj)
    add_ln_k<<<NROWS, blk>>>(x, proj, ln1_g, ln1_b, x1);
    // angles = LN3(x1) @ qin_w^T + qin_b
    ln3_qin_k<<<NROWS, blk>>>(x1, ln3_g, ln3_b, qin_w, qin_b, ang);
    // quantum expectation values
    quantum_k<<<NROWS / 8, blk>>>(ang, qweights, z);
    // x2 = x1 + z @ qout_w^T + qout_b
    qout_resid_k<<<NROWS, blk>>>(x1, z, qout_w, qout_b, x2);
    // FFN
    gemm_tf32<2><<<dim3(DFF / 128, NROWS / 128, 1), blk>>>(
        x2, D_, 0, 0, ffn_w1, D_, 0, 0, buf1, DFF, 0, 0, D_, ffn_b1, 1.0f);
    gemm_tf32<1><<<dim3(D_ / 128, NROWS / 128, 1), blk>>>(
        buf1, DFF, 0, 0, ffn_w2, DFF, 0, 0, ffn, D_, 0, 0, DFF, ffn_b2, 1.0f);
    // out = LN2(x2 + ffn)
    add_ln_k<<<NROWS, blk>>>(x2, ffn, ln2_g, ln2_b, out);
}